// round 13
// baseline (speedup 1.0000x reference)
#include <cuda_runtime.h>

// GraphSAGE 2-layer, N=100000, E=1600000, dims 32 -> 64 -> 32.
//   K0: zero g_agg
//   K1: scatter  g_agg[dst] += x[src]     (8 threads/edge, v4 RED atomics)
//   K2a: mlp1  h = relu(W1l@agg + b1 + W1r@x)        (thread/node, FFMA2)
//   K2b: mlp2  g_g = W2l@h ; out = W2r@h + b2        (thread/node, FFMA2)
//   K3: scatter  out[dst] += g_g[src]     (8 threads/edge, v4 RED atomics)
// MLP split in two kernels to keep live registers ~100 (no local-memory spills).
// Layer-2 projection applied BEFORE the scatter (linear commutes with sum).
// edge_index is int32 on device.

#define MAX_NODES 100000
#define D 32

typedef unsigned long long ull;

__device__ float g_agg[MAX_NODES * D];
__device__ float g_h[MAX_NODES * 64];
__device__ float g_g[MAX_NODES * D];

__device__ __forceinline__ void red_add_v4(float* addr, float4 v) {
    asm volatile("red.global.add.v4.f32 [%0], {%1, %2, %3, %4};"
                 :: "l"(addr), "f"(v.x), "f"(v.y), "f"(v.z), "f"(v.w)
                 : "memory");
}
__device__ __forceinline__ ull fma2(ull a, ull b, ull c) {
    ull d;
    asm("fma.rn.f32x2 %0, %1, %2, %3;" : "=l"(d) : "l"(a), "l"(b), "l"(c));
    return d;
}
__device__ __forceinline__ ull pack2(float lo, float hi) {
    ull d;
    asm("mov.b64 %0, {%1, %2};" : "=l"(d) : "f"(lo), "f"(hi));
    return d;
}
__device__ __forceinline__ void unpack2(ull v, float& lo, float& hi) {
    asm("mov.b64 {%0, %1}, %2;" : "=f"(lo), "=f"(hi) : "l"(v));
}

// ---------------------------------------------------------------------------
__global__ void zero_agg_kernel(int n4) {
    int i = blockIdx.x * blockDim.x + threadIdx.x;
    if (i < n4) ((float4*)g_agg)[i] = make_float4(0.f, 0.f, 0.f, 0.f);
}

// ---------------------------------------------------------------------------
// 8 threads per edge; quad q handles floats [4q, 4q+4). One v4 RED per thread.
__global__ void scatter_x_kernel(const float* __restrict__ x,
                                 const int* __restrict__ src,
                                 const int* __restrict__ dst,
                                 int E) {
    int t = blockIdx.x * blockDim.x + threadIdx.x;
    int e = t >> 3;
    int q = (t & 7) << 2;
    if (e >= E) return;
    int s = __ldg(&src[e]);
    int d = __ldg(&dst[e]);
    float4 v = *(const float4*)&x[s * D + q];
    red_add_v4(&g_agg[d * D + q], v);
}

__global__ void scatter_g_kernel(float* __restrict__ out,
                                 const int* __restrict__ src,
                                 const int* __restrict__ dst,
                                 int E) {
    int t = blockIdx.x * blockDim.x + threadIdx.x;
    int e = t >> 3;
    int q = (t & 7) << 2;
    if (e >= E) return;
    int s = __ldg(&src[e]);
    int d = __ldg(&dst[e]);
    float4 v = *(const float4*)&g_g[s * D + q];
    red_add_v4(&out[d * D + q], v);
}

// ---------------------------------------------------------------------------
// mlp1: h = relu(W1l@agg + b1 + W1r@x), thread per node, FFMA2.
// Inputs streamed float4-at-a-time inside the k loop to keep live regs low.
// smem: W1L[k*64+m] = Wli[m][k], W1R likewise (m contiguous -> packed pairs).
__global__ void __launch_bounds__(256)
mlp1_kernel(const float* __restrict__ x,
            const float* __restrict__ Wli,  // [64,32]
            const float* __restrict__ bli,  // [64]
            const float* __restrict__ Wri,  // [64,32]
            int N) {
    __shared__ longlong2 w1l[32][16];   // [k][m4]
    __shared__ longlong2 w1r[32][16];
    __shared__ ull b1p[32];

    int tid = threadIdx.x;
    {
        float* W1L = (float*)w1l;
        float* W1R = (float*)w1r;
        for (int idx = tid; idx < 2048; idx += 256) {
            int k = idx >> 6, m = idx & 63;
            W1L[k * 64 + m] = Wli[m * 32 + k];
            W1R[k * 64 + m] = Wri[m * 32 + k];
        }
        if (tid < 64) ((float*)b1p)[tid] = bli[tid];
    }
    __syncthreads();

    int node = blockIdx.x * 256 + tid;
    if (node >= N) return;

    ull h2[32];
    #pragma unroll
    for (int m2 = 0; m2 < 32; m2++) h2[m2] = b1p[m2];

    const float4* ar = (const float4*)&g_agg[node * D];
    const float4* xr = (const float4*)&x[node * D];

    #pragma unroll
    for (int k4 = 0; k4 < 8; k4++) {
        float4 a4 = __ldg(&ar[k4]);
        float4 x4 = __ldg(&xr[k4]);
        float fa[4] = {a4.x, a4.y, a4.z, a4.w};
        float fx[4] = {x4.x, x4.y, x4.z, x4.w};
        #pragma unroll
        for (int j = 0; j < 4; j++) {
            int k = 4 * k4 + j;
            ull av2 = pack2(fa[j], fa[j]);
            ull xx2 = pack2(fx[j], fx[j]);
            #pragma unroll
            for (int q = 0; q < 16; q++) {
                longlong2 wl = w1l[k][q];
                longlong2 wr = w1r[k][q];
                h2[2 * q]     = fma2((ull)wl.x, av2, h2[2 * q]);
                h2[2 * q + 1] = fma2((ull)wl.y, av2, h2[2 * q + 1]);
                h2[2 * q]     = fma2((ull)wr.x, xx2, h2[2 * q]);
                h2[2 * q + 1] = fma2((ull)wr.y, xx2, h2[2 * q + 1]);
            }
        }
    }

    // ReLU + store h (pairs)
    ull* hout = (ull*)&g_h[node * 64];
    #pragma unroll
    for (int m2 = 0; m2 < 32; m2++) {
        float lo, hi;
        unpack2(h2[m2], lo, hi);
        hout[m2] = pack2(fmaxf(lo, 0.0f), fmaxf(hi, 0.0f));
    }
}

// ---------------------------------------------------------------------------
// mlp2: g_g = W2l@h ; out = W2r@h + b2. h streamed float4-at-a-time.
// smem: W2L[m*32+o] = Wlo[o][m], W2R likewise.
__global__ void __launch_bounds__(256)
mlp2_kernel(const float* __restrict__ Wlo,  // [32,64]
            const float* __restrict__ blo,  // [32]
            const float* __restrict__ Wro,  // [32,64]
            float* __restrict__ out,
            int N) {
    __shared__ longlong2 w2l[64][8];    // [m][o4]
    __shared__ longlong2 w2r[64][8];
    __shared__ ull b2p[16];

    int tid = threadIdx.x;
    {
        float* W2L = (float*)w2l;
        float* W2R = (float*)w2r;
        for (int idx = tid; idx < 2048; idx += 256) {
            int m = idx >> 5, o = idx & 31;
            W2L[m * 32 + o] = Wlo[o * 64 + m];
            W2R[m * 32 + o] = Wro[o * 64 + m];
        }
        if (tid < 32) ((float*)b2p)[tid] = blo[tid];
    }
    __syncthreads();

    int node = blockIdx.x * 256 + tid;
    if (node >= N) return;

    ull g2[16], r2[16];
    #pragma unroll
    for (int o2 = 0; o2 < 16; o2++) { g2[o2] = 0ull; r2[o2] = b2p[o2]; }

    const float4* hr = (const float4*)&g_h[node * 64];
    #pragma unroll
    for (int m4 = 0; m4 < 16; m4++) {
        float4 h4 = __ldg(&hr[m4]);
        float fh[4] = {h4.x, h4.y, h4.z, h4.w};
        #pragma unroll
        for (int j = 0; j < 4; j++) {
            int m = 4 * m4 + j;
            ull hv2 = pack2(fh[j], fh[j]);
            #pragma unroll
            for (int q = 0; q < 8; q++) {
                longlong2 wl = w2l[m][q];
                longlong2 wr = w2r[m][q];
                g2[2 * q]     = fma2((ull)wl.x, hv2, g2[2 * q]);
                g2[2 * q + 1] = fma2((ull)wl.y, hv2, g2[2 * q + 1]);
                r2[2 * q]     = fma2((ull)wr.x, hv2, r2[2 * q]);
                r2[2 * q + 1] = fma2((ull)wr.y, hv2, r2[2 * q + 1]);
            }
        }
    }

    ull* gg = (ull*)&g_g[node * D];
    ull* oo = (ull*)&out[node * D];
    #pragma unroll
    for (int o2 = 0; o2 < 16; o2++) {
        gg[o2] = g2[o2];
        oo[o2] = r2[o2];
    }
}

// ---------------------------------------------------------------------------
extern "C" void kernel_launch(void* const* d_in, const int* in_sizes, int n_in,
                              void* d_out, int out_size) {
    const float* x   = (const float*)d_in[0];
    const int*   ei  = (const int*)d_in[1];
    const float* Wli = (const float*)d_in[2];
    const float* bli = (const float*)d_in[3];
    const float* Wri = (const float*)d_in[4];
    const float* Wlo = (const float*)d_in[5];
    const float* blo = (const float*)d_in[6];
    const float* Wro = (const float*)d_in[7];
    float* out = (float*)d_out;

    int N = in_sizes[0] / D;      // 100000
    int E = in_sizes[1] / 2;      // 1600000
    const int* src = ei;
    const int* dst = ei + E;

    {   // K0: zero aggregation buffer
        int n4 = N * D / 4;
        zero_agg_kernel<<<(n4 + 255) / 256, 256>>>(n4);
    }
    {   // K1: scatter x into g_agg — 8 threads/edge
        int blocks = (E + 31) / 32;
        scatter_x_kernel<<<blocks, 256>>>(x, src, dst, E);
    }
    {   // K2a/K2b: split MLP (thread per node, FFMA2, no spills)
        mlp1_kernel<<<(N + 255) / 256, 256>>>(x, Wli, bli, Wri, N);
        mlp2_kernel<<<(N + 255) / 256, 256>>>(Wlo, blo, Wro, out, N);
    }
    {   // K3: scatter g into out
        int blocks = (E + 31) / 32;
        scatter_g_kernel<<<blocks, 256>>>(out, src, dst, E);
    }
}

// round 14
// speedup vs baseline: 2.0661x; 2.0661x over previous
#include <cuda_runtime.h>

// GraphSAGE 2-layer, N=100000, E=1600000, dims 32 -> 64 -> 32.
//   K0: zero g_agg
//   K1: scatter  g_agg[dst] += x[src]      (8 threads/edge, v4 RED atomics)
//   K2: fused block-tiled GEMM MLP (128 nodes/block, 8x8 register tiles, FFMA2)
//        stage1: h = relu([W1l|W1r] @ [agg;x] + b1)   (K=64 -> 64)
//        stage2: [g|r] = [W2l;W2r] @ h (+[0;b2])       (K=64 -> 64)
//   K3: scatter  out[dst] += g_g[src]      (8 threads/edge, v4 RED atomics)
// Layer-2 projection applied BEFORE the scatter (linear commutes with sum).
// edge_index is int32 on device.

#define MAX_NODES 100000
#define D 32

typedef unsigned long long ull;

__device__ float g_agg[MAX_NODES * D];
__device__ float g_g[MAX_NODES * D];

__device__ __forceinline__ void red_add_v4(float* addr, float4 v) {
    asm volatile("red.global.add.v4.f32 [%0], {%1, %2, %3, %4};"
                 :: "l"(addr), "f"(v.x), "f"(v.y), "f"(v.z), "f"(v.w)
                 : "memory");
}
__device__ __forceinline__ ull fma2(ull a, ull b, ull c) {
    ull d;
    asm("fma.rn.f32x2 %0, %1, %2, %3;" : "=l"(d) : "l"(a), "l"(b), "l"(c));
    return d;
}
__device__ __forceinline__ ull pack2(float lo, float hi) {
    ull d;
    asm("mov.b64 %0, {%1, %2};" : "=l"(d) : "f"(lo), "f"(hi));
    return d;
}
__device__ __forceinline__ ull pack2s(float v) {
    ull d;
    asm("mov.b64 %0, {%1, %1};" : "=l"(d) : "f"(v));
    return d;
}
__device__ __forceinline__ void unpack2(ull v, float& lo, float& hi) {
    asm("mov.b64 {%0, %1}, %2;" : "=f"(lo), "=f"(hi) : "l"(v));
}

// ---------------------------------------------------------------------------
__global__ void zero_agg_kernel(int n4) {
    int i = blockIdx.x * blockDim.x + threadIdx.x;
    if (i < n4) ((float4*)g_agg)[i] = make_float4(0.f, 0.f, 0.f, 0.f);
}

// ---------------------------------------------------------------------------
__global__ void scatter_x_kernel(const float* __restrict__ x,
                                 const int* __restrict__ src,
                                 const int* __restrict__ dst,
                                 int E) {
    int t = blockIdx.x * blockDim.x + threadIdx.x;
    int e = t >> 3;
    int q = (t & 7) << 2;
    if (e >= E) return;
    int s = __ldg(&src[e]);
    int d = __ldg(&dst[e]);
    float4 v = *(const float4*)&x[s * D + q];
    red_add_v4(&g_agg[d * D + q], v);
}

__global__ void scatter_g_kernel(float* __restrict__ out,
                                 const int* __restrict__ src,
                                 const int* __restrict__ dst,
                                 int E) {
    int t = blockIdx.x * blockDim.x + threadIdx.x;
    int e = t >> 3;
    int q = (t & 7) << 2;
    if (e >= E) return;
    int s = __ldg(&src[e]);
    int d = __ldg(&dst[e]);
    float4 v = *(const float4*)&g_g[s * D + q];
    red_add_v4(&out[d * D + q], v);
}

// ---------------------------------------------------------------------------
// Fused GEMM MLP. Block = 128 threads = 128 nodes. Thread tile: 8 nodes x 8 outs.
// smem:
//   At [64][132] floats: transposed inputs A_t[k][node] (stage1: [agg|x]);
//                        reused as h_t[k][node] for stage2.
//   w1 [64][32] ull:   w1[k][m2] = pack2(W1[2m2][k], W1[2m2+1][k]), W1=[Wli|Wri]
//   w2 [64][32] ull:   combined [Wlo;Wro] likewise (K = hidden 64)
//   b1p[32], b2p[32] ull: output-pair biases (stage2: 0 for g-half, blo for r-half)
#define AT_PITCH 132
#define SM_AT    0
#define SM_W1    (64 * AT_PITCH * 4)                 // 33792
#define SM_W2    (SM_W1 + 64 * 32 * 8)               // +16384
#define SM_B1    (SM_W2 + 64 * 32 * 8)               // +16384
#define SM_B2    (SM_B1 + 32 * 8)
#define SM_TOTAL (SM_B2 + 32 * 8)                    // 67072

__global__ void __launch_bounds__(128)
gemm_mlp_kernel(const float* __restrict__ x,
                const float* __restrict__ Wli,  // [64,32]
                const float* __restrict__ bli,  // [64]
                const float* __restrict__ Wri,  // [64,32]
                const float* __restrict__ Wlo,  // [32,64]
                const float* __restrict__ blo,  // [32]
                const float* __restrict__ Wro,  // [32,64]
                float* __restrict__ out,
                int N) {
    extern __shared__ char sm[];
    float* At = (float*)(sm + SM_AT);
    ull* w1   = (ull*)(sm + SM_W1);
    ull* w2   = (ull*)(sm + SM_W2);
    ull* b1p  = (ull*)(sm + SM_B1);
    ull* b2p  = (ull*)(sm + SM_B2);

    int tid = threadIdx.x;

    // ---- stage weights (k-fastest -> coalesced global reads) ----
    for (int i = tid; i < 2048; i += 128) {
        int k = i & 63, m2 = i >> 6;     // m2 = output pair 0..31
        int m0 = 2 * m2, m1 = 2 * m2 + 1;
        float a0 = (k < 32) ? Wli[m0 * 32 + k] : Wri[m0 * 32 + k - 32];
        float a1 = (k < 32) ? Wli[m1 * 32 + k] : Wri[m1 * 32 + k - 32];
        w1[k * 32 + m2] = pack2(a0, a1);
        float c0 = (m0 < 32) ? Wlo[m0 * 64 + k] : Wro[(m0 - 32) * 64 + k];
        float c1 = (m1 < 32) ? Wlo[m1 * 64 + k] : Wro[(m1 - 32) * 64 + k];
        w2[k * 32 + m2] = pack2(c0, c1);
    }
    if (tid < 32) {
        b1p[tid] = pack2(bli[2 * tid], bli[2 * tid + 1]);
        b2p[tid] = (tid < 16) ? 0ull
                              : pack2(blo[2 * tid - 32], blo[2 * tid - 31]);
    }

    // ---- stage inputs transposed: At[k][node] ----
    {
        int node = blockIdx.x * 128 + tid;
        if (node < N) {
            const float4* ar = (const float4*)&g_agg[node * D];
            const float4* xr = (const float4*)&x[node * D];
            #pragma unroll
            for (int c = 0; c < 8; c++) {
                float4 v = __ldg(&ar[c]);
                At[(4 * c + 0) * AT_PITCH + tid] = v.x;
                At[(4 * c + 1) * AT_PITCH + tid] = v.y;
                At[(4 * c + 2) * AT_PITCH + tid] = v.z;
                At[(4 * c + 3) * AT_PITCH + tid] = v.w;
            }
            #pragma unroll
            for (int c = 0; c < 8; c++) {
                float4 v = __ldg(&xr[c]);
                At[(32 + 4 * c + 0) * AT_PITCH + tid] = v.x;
                At[(32 + 4 * c + 1) * AT_PITCH + tid] = v.y;
                At[(32 + 4 * c + 2) * AT_PITCH + tid] = v.z;
                At[(32 + 4 * c + 3) * AT_PITCH + tid] = v.w;
            }
        } else {
            #pragma unroll
            for (int k = 0; k < 64; k++) At[k * AT_PITCH + tid] = 0.0f;
        }
    }
    __syncthreads();

    int n8 = tid & 15;          // node group: nodes n8*8 .. n8*8+7 (within tile)
    int o8 = tid >> 4;          // output group: outputs o8*8 .. o8*8+7

    // ---- stage 1: h = relu(W1 @ A + b1) ----
    ull acc[8][4];
    #pragma unroll
    for (int n = 0; n < 8; n++)
        #pragma unroll
        for (int j = 0; j < 4; j++) acc[n][j] = b1p[o8 * 4 + j];

    #pragma unroll 4
    for (int k = 0; k < 64; k++) {
        const float* arow = &At[k * AT_PITCH + n8 * 8];
        float4 a0 = *(const float4*)arow;
        float4 a1 = *(const float4*)(arow + 4);
        ull ap[8];
        ap[0] = pack2s(a0.x); ap[1] = pack2s(a0.y);
        ap[2] = pack2s(a0.z); ap[3] = pack2s(a0.w);
        ap[4] = pack2s(a1.x); ap[5] = pack2s(a1.y);
        ap[6] = pack2s(a1.z); ap[7] = pack2s(a1.w);
        const ull* wrow = &w1[k * 32 + o8 * 4];
        ull wv0 = wrow[0], wv1 = wrow[1], wv2 = wrow[2], wv3 = wrow[3];
        #pragma unroll
        for (int n = 0; n < 8; n++) {
            acc[n][0] = fma2(ap[n], wv0, acc[n][0]);
            acc[n][1] = fma2(ap[n], wv1, acc[n][1]);
            acc[n][2] = fma2(ap[n], wv2, acc[n][2]);
            acc[n][3] = fma2(ap[n], wv3, acc[n][3]);
        }
    }

    __syncthreads();   // all At reads done; safe to overwrite with h_t

    // relu + write h_t[k=output][node]
    #pragma unroll
    for (int n = 0; n < 8; n++) {
        #pragma unroll
        for (int j = 0; j < 4; j++) {
            float lo, hi;
            unpack2(acc[n][j], lo, hi);
            At[(o8 * 8 + 2 * j)     * AT_PITCH + n8 * 8 + n] = fmaxf(lo, 0.0f);
            At[(o8 * 8 + 2 * j + 1) * AT_PITCH + n8 * 8 + n] = fmaxf(hi, 0.0f);
        }
    }
    __syncthreads();

    // ---- stage 2: [g|r] = W2 @ h (+ bias) ----
    #pragma unroll
    for (int n = 0; n < 8; n++)
        #pragma unroll
        for (int j = 0; j < 4; j++) acc[n][j] = b2p[o8 * 4 + j];

    #pragma unroll 4
    for (int k = 0; k < 64; k++) {
        const float* arow = &At[k * AT_PITCH + n8 * 8];
        float4 a0 = *(const float4*)arow;
        float4 a1 = *(const float4*)(arow + 4);
        ull ap[8];
        ap[0] = pack2s(a0.x); ap[1] = pack2s(a0.y);
        ap[2] = pack2s(a0.z); ap[3] = pack2s(a0.w);
        ap[4] = pack2s(a1.x); ap[5] = pack2s(a1.y);
        ap[6] = pack2s(a1.z); ap[7] = pack2s(a1.w);
        const ull* wrow = &w2[k * 32 + o8 * 4];
        ull wv0 = wrow[0], wv1 = wrow[1], wv2 = wrow[2], wv3 = wrow[3];
        #pragma unroll
        for (int n = 0; n < 8; n++) {
            acc[n][0] = fma2(ap[n], wv0, acc[n][0]);
            acc[n][1] = fma2(ap[n], wv1, acc[n][1]);
            acc[n][2] = fma2(ap[n], wv2, acc[n][2]);
            acc[n][3] = fma2(ap[n], wv3, acc[n][3]);
        }
    }

    // ---- write results: outputs o8*8..+7; o8<4 -> g_g, o8>=4 -> out ----
    int nbase = blockIdx.x * 128 + n8 * 8;
    #pragma unroll
    for (int n = 0; n < 8; n++) {
        int node = nbase + n;
        if (node >= N) break;
        float l0, h0, l1, h1, l2, h2, l3, h3;
        unpack2(acc[n][0], l0, h0);
        unpack2(acc[n][1], l1, h1);
        unpack2(acc[n][2], l2, h2);
        unpack2(acc[n][3], l3, h3);
        float4 v0 = make_float4(l0, h0, l1, h1);
        float4 v1 = make_float4(l2, h2, l3, h3);
        if (o8 < 4) {
            float* p = &g_g[node * D + o8 * 8];
            *(float4*)p = v0;
            *(float4*)(p + 4) = v1;
        } else {
            float* p = &out[node * D + (o8 - 4) * 8];
            *(float4*)p = v0;
            *(float4*)(p + 4) = v1;
        }
    }
}

// ---------------------------------------------------------------------------
extern "C" void kernel_launch(void* const* d_in, const int* in_sizes, int n_in,
                              void* d_out, int out_size) {
    const float* x   = (const float*)d_in[0];
    const int*   ei  = (const int*)d_in[1];
    const float* Wli = (const float*)d_in[2];
    const float* bli = (const float*)d_in[3];
    const float* Wri = (const float*)d_in[4];
    const float* Wlo = (const float*)d_in[5];
    const float* blo = (const float*)d_in[6];
    const float* Wro = (const float*)d_in[7];
    float* out = (float*)d_out;

    int N = in_sizes[0] / D;      // 100000
    int E = in_sizes[1] / 2;      // 1600000
    const int* src = ei;
    const int* dst = ei + E;

    static bool attr_set = false;
    if (!attr_set) {
        cudaFuncSetAttribute(gemm_mlp_kernel,
                             cudaFuncAttributeMaxDynamicSharedMemorySize,
                             SM_TOTAL);
        attr_set = true;
    }

    {   // K0: zero aggregation buffer
        int n4 = N * D / 4;
        zero_agg_kernel<<<(n4 + 255) / 256, 256>>>(n4);
    }
    {   // K1: scatter x into g_agg
        int blocks = (E + 31) / 32;
        scatter_x_kernel<<<blocks, 256>>>(x, src, dst, E);
    }
    {   // K2: fused GEMM MLP
        int blocks = (N + 127) / 128;
        gemm_mlp_kernel<<<blocks, 128, SM_TOTAL>>>(x, Wli, bli, Wri,
                                                   Wlo, blo, Wro, out, N);
    }
    {   // K3: scatter g into out
        int blocks = (E + 31) / 32;
        scatter_g_kernel<<<blocks, 256>>>(out, src, dst, E);
    }
}

// round 16
// speedup vs baseline: 2.2936x; 1.1101x over previous
#include <cuda_runtime.h>
#include <cuda_fp16.h>

// GraphSAGE 2-layer, N=100000, E=1600000, dims 32 -> 64 -> 32.
//   K0: prep    zero g_aggh (fp16) + convert x -> xh (fp16)
//   K1: scatter g_aggh[dst] += xh[src]   (4 threads/edge, v4.f16x2 RED = 8 halves/op)
//   K2: fused block-tiled GEMM MLP (128 nodes/block, 8x8 tiles, FFMA2);
//       reads agg as fp16, x as fp32 (exact lin_r path)
//   K3: scatter out[dst] += g_g[src]     (8 threads/edge, v4.f32 RED, full precision)
// Layer-2 projection applied BEFORE the scatter (linear commutes with sum).
// edge_index is int32 on device.

#define MAX_NODES 100000
#define D 32

typedef unsigned long long ull;

__device__ __half g_aggh[MAX_NODES * D];   // fp16 aggregation buffer
__device__ __half g_xh[MAX_NODES * D];     // fp16 copy of x (scatter payload)
__device__ float  g_g[MAX_NODES * D];

__device__ __forceinline__ void red_add_v4(float* addr, float4 v) {
    asm volatile("red.global.add.v4.f32 [%0], {%1, %2, %3, %4};"
                 :: "l"(addr), "f"(v.x), "f"(v.y), "f"(v.z), "f"(v.w)
                 : "memory");
}
__device__ __forceinline__ void red_add_v4h2(__half* addr, uint4 v) {
    asm volatile("red.global.add.noftz.v4.f16x2 [%0], {%1, %2, %3, %4};"
                 :: "l"(addr), "r"(v.x), "r"(v.y), "r"(v.z), "r"(v.w)
                 : "memory");
}
__device__ __forceinline__ ull fma2(ull a, ull b, ull c) {
    ull d;
    asm("fma.rn.f32x2 %0, %1, %2, %3;" : "=l"(d) : "l"(a), "l"(b), "l"(c));
    return d;
}
__device__ __forceinline__ ull pack2(float lo, float hi) {
    ull d;
    asm("mov.b64 %0, {%1, %2};" : "=l"(d) : "f"(lo), "f"(hi));
    return d;
}
__device__ __forceinline__ ull pack2s(float v) {
    ull d;
    asm("mov.b64 %0, {%1, %1};" : "=l"(d) : "f"(v));
    return d;
}
__device__ __forceinline__ void unpack2(ull v, float& lo, float& hi) {
    asm("mov.b64 {%0, %1}, %2;" : "=f"(lo), "=f"(hi) : "l"(v));
}

// ---------------------------------------------------------------------------
// prep: zero g_aggh and convert x -> xh. Unit = 8 halves (uint4) = 8 floats.
__global__ void prep_kernel(const float* __restrict__ x, int n8) {
    int i = blockIdx.x * blockDim.x + threadIdx.x;
    if (i >= n8) return;
    ((uint4*)g_aggh)[i] = make_uint4(0u, 0u, 0u, 0u);
    const float4* xp = (const float4*)x;
    float4 a = __ldg(&xp[2 * i]);
    float4 b = __ldg(&xp[2 * i + 1]);
    __half2 h0 = __floats2half2_rn(a.x, a.y);
    __half2 h1 = __floats2half2_rn(a.z, a.w);
    __half2 h2 = __floats2half2_rn(b.x, b.y);
    __half2 h3 = __floats2half2_rn(b.z, b.w);
    uint4 o;
    o.x = *(unsigned*)&h0; o.y = *(unsigned*)&h1;
    o.z = *(unsigned*)&h2; o.w = *(unsigned*)&h3;
    ((uint4*)g_xh)[i] = o;
}

// ---------------------------------------------------------------------------
// Layer-1 scatter, fp16: 4 threads/edge, thread q handles halves [8q, 8q+8).
__global__ void scatter_x_kernel(const int* __restrict__ src,
                                 const int* __restrict__ dst,
                                 int E) {
    int t = blockIdx.x * blockDim.x + threadIdx.x;
    int e = t >> 2;
    int q = (t & 3) << 3;          // half offset: 0,8,16,24
    if (e >= E) return;
    int s = __ldg(&src[e]);
    int d = __ldg(&dst[e]);
    uint4 v = __ldg((const uint4*)&g_xh[s * D + q]);
    red_add_v4h2(&g_aggh[d * D + q], v);
}

// Layer-2 scatter, fp32 (unchanged): 8 threads/edge, float4 each.
__global__ void scatter_g_kernel(float* __restrict__ out,
                                 const int* __restrict__ src,
                                 const int* __restrict__ dst,
                                 int E) {
    int t = blockIdx.x * blockDim.x + threadIdx.x;
    int e = t >> 3;
    int q = (t & 7) << 2;
    if (e >= E) return;
    int s = __ldg(&src[e]);
    int d = __ldg(&dst[e]);
    float4 v = *(const float4*)&g_g[s * D + q];
    red_add_v4(&out[d * D + q], v);
}

// ---------------------------------------------------------------------------
// Fused GEMM MLP. Block = 128 threads = 128 nodes. Thread tile: 8 nodes x 8 outs.
#define AT_PITCH 132
#define SM_AT    0
#define SM_W1    (64 * AT_PITCH * 4)                 // 33792
#define SM_W2    (SM_W1 + 64 * 32 * 8)
#define SM_B1    (SM_W2 + 64 * 32 * 8)
#define SM_B2    (SM_B1 + 32 * 8)
#define SM_TOTAL (SM_B2 + 32 * 8)                    // 67072

__global__ void __launch_bounds__(128)
gemm_mlp_kernel(const float* __restrict__ x,
                const float* __restrict__ Wli,  // [64,32]
                const float* __restrict__ bli,  // [64]
                const float* __restrict__ Wri,  // [64,32]
                const float* __restrict__ Wlo,  // [32,64]
                const float* __restrict__ blo,  // [32]
                const float* __restrict__ Wro,  // [32,64]
                float* __restrict__ out,
                int N) {
    extern __shared__ char sm[];
    float* At = (float*)(sm + SM_AT);
    ull* w1   = (ull*)(sm + SM_W1);
    ull* w2   = (ull*)(sm + SM_W2);
    ull* b1p  = (ull*)(sm + SM_B1);
    ull* b2p  = (ull*)(sm + SM_B2);

    int tid = threadIdx.x;

    // ---- stage weights (k-fastest -> coalesced) ----
    for (int i = tid; i < 2048; i += 128) {
        int k = i & 63, m2 = i >> 6;
        int m0 = 2 * m2, m1 = 2 * m2 + 1;
        float a0 = (k < 32) ? Wli[m0 * 32 + k] : Wri[m0 * 32 + k - 32];
        float a1 = (k < 32) ? Wli[m1 * 32 + k] : Wri[m1 * 32 + k - 32];
        w1[k * 32 + m2] = pack2(a0, a1);
        float c0 = (m0 < 32) ? Wlo[m0 * 64 + k] : Wro[(m0 - 32) * 64 + k];
        float c1 = (m1 < 32) ? Wlo[m1 * 64 + k] : Wro[(m1 - 32) * 64 + k];
        w2[k * 32 + m2] = pack2(c0, c1);
    }
    if (tid < 32) {
        b1p[tid] = pack2(bli[2 * tid], bli[2 * tid + 1]);
        b2p[tid] = (tid < 16) ? 0ull
                              : pack2(blo[2 * tid - 32], blo[2 * tid - 31]);
    }

    // ---- stage inputs transposed: At[k][node]; agg from fp16, x fp32 ----
    {
        int node = blockIdx.x * 128 + tid;
        if (node < N) {
            const uint4* ar = (const uint4*)&g_aggh[node * D];   // 4 x 8 halves
            const float4* xr = (const float4*)&x[node * D];
            #pragma unroll
            for (int c = 0; c < 4; c++) {
                uint4 u = __ldg(&ar[c]);
                float2 f0 = __half22float2(*(__half2*)&u.x);
                float2 f1 = __half22float2(*(__half2*)&u.y);
                float2 f2 = __half22float2(*(__half2*)&u.z);
                float2 f3 = __half22float2(*(__half2*)&u.w);
                At[(8 * c + 0) * AT_PITCH + tid] = f0.x;
                At[(8 * c + 1) * AT_PITCH + tid] = f0.y;
                At[(8 * c + 2) * AT_PITCH + tid] = f1.x;
                At[(8 * c + 3) * AT_PITCH + tid] = f1.y;
                At[(8 * c + 4) * AT_PITCH + tid] = f2.x;
                At[(8 * c + 5) * AT_PITCH + tid] = f2.y;
                At[(8 * c + 6) * AT_PITCH + tid] = f3.x;
                At[(8 * c + 7) * AT_PITCH + tid] = f3.y;
            }
            #pragma unroll
            for (int c = 0; c < 8; c++) {
                float4 v = __ldg(&xr[c]);
                At[(32 + 4 * c + 0) * AT_PITCH + tid] = v.x;
                At[(32 + 4 * c + 1) * AT_PITCH + tid] = v.y;
                At[(32 + 4 * c + 2) * AT_PITCH + tid] = v.z;
                At[(32 + 4 * c + 3) * AT_PITCH + tid] = v.w;
            }
        } else {
            #pragma unroll
            for (int k = 0; k < 64; k++) At[k * AT_PITCH + tid] = 0.0f;
        }
    }
    __syncthreads();

    int n8 = tid & 15;          // node group
    int o8 = tid >> 4;          // output group

    // ---- stage 1: h = relu(W1 @ A + b1) ----
    ull acc[8][4];
    #pragma unroll
    for (int n = 0; n < 8; n++)
        #pragma unroll
        for (int j = 0; j < 4; j++) acc[n][j] = b1p[o8 * 4 + j];

    #pragma unroll 4
    for (int k = 0; k < 64; k++) {
        const float* arow = &At[k * AT_PITCH + n8 * 8];
        float4 a0 = *(const float4*)arow;
        float4 a1 = *(const float4*)(arow + 4);
        ull ap[8];
        ap[0] = pack2s(a0.x); ap[1] = pack2s(a0.y);
        ap[2] = pack2s(a0.z); ap[3] = pack2s(a0.w);
        ap[4] = pack2s(a1.x); ap[5] = pack2s(a1.y);
        ap[6] = pack2s(a1.z); ap[7] = pack2s(a1.w);
        const ull* wrow = &w1[k * 32 + o8 * 4];
        ull wv0 = wrow[0], wv1 = wrow[1], wv2 = wrow[2], wv3 = wrow[3];
        #pragma unroll
        for (int n = 0; n < 8; n++) {
            acc[n][0] = fma2(ap[n], wv0, acc[n][0]);
            acc[n][1] = fma2(ap[n], wv1, acc[n][1]);
            acc[n][2] = fma2(ap[n], wv2, acc[n][2]);
            acc[n][3] = fma2(ap[n], wv3, acc[n][3]);
        }
    }

    __syncthreads();

    // relu + write h_t[k=output][node]
    #pragma unroll
    for (int n = 0; n < 8; n++) {
        #pragma unroll
        for (int j = 0; j < 4; j++) {
            float lo, hi;
            unpack2(acc[n][j], lo, hi);
            At[(o8 * 8 + 2 * j)     * AT_PITCH + n8 * 8 + n] = fmaxf(lo, 0.0f);
            At[(o8 * 8 + 2 * j + 1) * AT_PITCH + n8 * 8 + n] = fmaxf(hi, 0.0f);
        }
    }
    __syncthreads();

    // ---- stage 2: [g|r] = W2 @ h (+ bias) ----
    #pragma unroll
    for (int n = 0; n < 8; n++)
        #pragma unroll
        for (int j = 0; j < 4; j++) acc[n][j] = b2p[o8 * 4 + j];

    #pragma unroll 4
    for (int k = 0; k < 64; k++) {
        const float* arow = &At[k * AT_PITCH + n8 * 8];
        float4 a0 = *(const float4*)arow;
        float4 a1 = *(const float4*)(arow + 4);
        ull ap[8];
        ap[0] = pack2s(a0.x); ap[1] = pack2s(a0.y);
        ap[2] = pack2s(a0.z); ap[3] = pack2s(a0.w);
        ap[4] = pack2s(a1.x); ap[5] = pack2s(a1.y);
        ap[6] = pack2s(a1.z); ap[7] = pack2s(a1.w);
        const ull* wrow = &w2[k * 32 + o8 * 4];
        ull wv0 = wrow[0], wv1 = wrow[1], wv2 = wrow[2], wv3 = wrow[3];
        #pragma unroll
        for (int n = 0; n < 8; n++) {
            acc[n][0] = fma2(ap[n], wv0, acc[n][0]);
            acc[n][1] = fma2(ap[n], wv1, acc[n][1]);
            acc[n][2] = fma2(ap[n], wv2, acc[n][2]);
            acc[n][3] = fma2(ap[n], wv3, acc[n][3]);
        }
    }

    // ---- write results: o8<4 -> g_g, o8>=4 -> out ----
    int nbase = blockIdx.x * 128 + n8 * 8;
    #pragma unroll
    for (int n = 0; n < 8; n++) {
        int node = nbase + n;
        if (node >= N) break;
        float l0, h0, l1, h1, l2, h2, l3, h3;
        unpack2(acc[n][0], l0, h0);
        unpack2(acc[n][1], l1, h1);
        unpack2(acc[n][2], l2, h2);
        unpack2(acc[n][3], l3, h3);
        float4 v0 = make_float4(l0, h0, l1, h1);
        float4 v1 = make_float4(l2, h2, l3, h3);
        if (o8 < 4) {
            float* p = &g_g[node * D + o8 * 8];
            *(float4*)p = v0;
            *(float4*)(p + 4) = v1;
        } else {
            float* p = &out[node * D + (o8 - 4) * 8];
            *(float4*)p = v0;
            *(float4*)(p + 4) = v1;
        }
    }
}

// ---------------------------------------------------------------------------
extern "C" void kernel_launch(void* const* d_in, const int* in_sizes, int n_in,
                              void* d_out, int out_size) {
    const float* x   = (const float*)d_in[0];
    const int*   ei  = (const int*)d_in[1];
    const float* Wli = (const float*)d_in[2];
    const float* bli = (const float*)d_in[3];
    const float* Wri = (const float*)d_in[4];
    const float* Wlo = (const float*)d_in[5];
    const float* blo = (const float*)d_in[6];
    const float* Wro = (const float*)d_in[7];
    float* out = (float*)d_out;

    int N = in_sizes[0] / D;      // 100000
    int E = in_sizes[1] / 2;      // 1600000
    const int* src = ei;
    const int* dst = ei + E;

    static bool attr_set = false;
    if (!attr_set) {
        cudaFuncSetAttribute(gemm_mlp_kernel,
                             cudaFuncAttributeMaxDynamicSharedMemorySize,
                             SM_TOTAL);
        attr_set = true;
    }

    {   // K0: zero fp16 agg + convert x -> fp16
        int n8 = N * D / 8;
        prep_kernel<<<(n8 + 255) / 256, 256>>>(x, n8);
    }
    {   // K1: layer-1 scatter (fp16x2 REDs) — 4 threads/edge
        int blocks = (E + 63) / 64;
        scatter_x_kernel<<<blocks, 256>>>(src, dst, E);
    }
    {   // K2: fused GEMM MLP
        int blocks = (N + 127) / 128;
        gemm_mlp_kernel<<<blocks, 128, SM_TOTAL>>>(x, Wli, bli, Wri,
                                                   Wlo, blo, Wro, out, N);
    }
    {   // K3: layer-2 scatter (fp32 REDs) — 8 threads/edge
        int blocks = (E + 31) / 32;
        scatter_g_kernel<<<blocks, 256>>>(out, src, dst, E);
    }
}